// round 10
// baseline (speedup 1.0000x reference)
#include <cuda_runtime.h>
#include <cstdint>

#define IN_F  4096
#define OUT_F 16384
#define NB    8      // batch vectors
#define RPW   4      // rows per warp
#define WARPS 8
#define THREADS (WARPS * 32)          // 256
#define ROWS_PER_CTA (RPW * WARPS)    // 32
#define NCHUNK (IN_F / 128)           // 32 chunks (4 cols/lane each)
#define AROW   (IN_F / 64)            // absmax row stride (64)

__constant__ float NF4_CODE[16] = {
    -1.0f, -0.6961928009986877f, -0.5250730514526367f, -0.39491748809814453f,
    -0.28444138169288635f, -0.18477343022823334f, -0.09105003625154495f, 0.0f,
    0.07958029955625534f, 0.16093020141124725f, 0.24611230194568634f,
    0.33791524171829224f, 0.44070982933044434f, 0.5626170039176941f,
    0.7229568362236023f, 1.0f};

typedef unsigned long long ull;

__device__ __forceinline__ ull pk2(float lo, float hi) {
    ull r;
    asm("mov.b64 %0, {%1, %2};" : "=l"(r)
        : "r"(__float_as_uint(lo)), "r"(__float_as_uint(hi)));
    return r;
}
__device__ __forceinline__ void upk2(ull v, float& lo, float& hi) {
    unsigned int a, b;
    asm("mov.b64 {%0, %1}, %2;" : "=r"(a), "=r"(b) : "l"(v));
    lo = __uint_as_float(a); hi = __uint_as_float(b);
}
__device__ __forceinline__ void fma2(ull& acc, ull a, ull b) {
    asm("fma.rn.f32x2 %0, %1, %2, %0;" : "+l"(acc) : "l"(a), "l"(b));
}
__device__ __forceinline__ ull mul2(ull a, ull b) {
    ull r;
    asm("mul.rn.f32x2 %0, %1, %2;" : "=l"(r) : "l"(a), "l"(b));
    return r;
}

__global__ __launch_bounds__(THREADS, 2)
void nf4_qlinear_kernel(const float* __restrict__ x,
                        const int*   __restrict__ codes,
                        const float* __restrict__ absmax,
                        float*       __restrict__ out) {
    // Packed-pair NF4 table: tab2[(c0<<4)|c1] = (nf4[c0], nf4[c1])
    __shared__ ull tab2[256];
    const int tid  = threadIdx.x;
    const int lane = tid & 31;
    const int warp = tid >> 5;
    for (int i = tid; i < 256; i += THREADS)
        tab2[i] = pk2(NF4_CODE[i >> 4], NF4_CODE[i & 15]);
    __syncthreads();

    const int row0   = blockIdx.x * ROWS_PER_CTA + warp * RPW;
    const int sel_hi = (lane >= 16);

    // Pointer-bump bases: every load below is reg + compile-time-const offset
    const int4*  cp = reinterpret_cast<const int4*>(
                          codes + (size_t)row0 * IN_F) + lane;
    const float* xp = x + lane * 4;
    const float* ap = absmax + (size_t)row0 * AROW + sel_hi;

    // acc[r][b] packs (even-col, odd-col) partial dot products
    ull acc[RPW][NB];
    #pragma unroll
    for (int r = 0; r < RPW; ++r)
        #pragma unroll
        for (int b = 0; b < NB; ++b) acc[r][b] = 0ULL;

    // ---- consume one chunk given prefetched codes+absmax and x offset ----
    auto consume = [&](const int4* cv, const float* am, int xo) {
        ull w01[RPW], w23[RPW];
        #pragma unroll
        for (int r = 0; r < RPW; ++r) {
            const ull a2 = pk2(am[r], am[r]);
            w01[r] = mul2(tab2[(cv[r].x << 4) | cv[r].y], a2);
            w23[r] = mul2(tab2[(cv[r].z << 4) | cv[r].w], a2);
        }
        #pragma unroll
        for (int b = 0; b < NB; ++b) {
            const ulonglong2 xv = *reinterpret_cast<const ulonglong2*>(
                xp + xo + (size_t)b * IN_F);
            #pragma unroll
            for (int r = 0; r < RPW; ++r) {
                fma2(acc[r][b], w01[r], xv.x);
                fma2(acc[r][b], w23[r], xv.y);
            }
        }
    };

    // ---- distance-1 double-buffered prefetch, unrolled x2 (no copies) ----
    int4  cvA[RPW], cvB[RPW];
    float amA[RPW], amB[RPW];
    #pragma unroll
    for (int r = 0; r < RPW; ++r) {
        cvA[r] = __ldcs(cp + r * (IN_F / 4));
        amA[r] = __ldg(ap + r * AROW);
    }

    #pragma unroll 1
    for (int j = 0; j < NCHUNK; j += 2) {
        // prefetch chunk j+1 (flies under consume of j)
        #pragma unroll
        for (int r = 0; r < RPW; ++r) {
            cvB[r] = __ldcs(cp + 32 + r * (IN_F / 4));
            amB[r] = __ldg(ap + 2 + r * AROW);
        }
        consume(cvA, amA, 0);

        // prefetch chunk j+2 (flies under consume of j+1)
        if (j + 2 < NCHUNK) {
            #pragma unroll
            for (int r = 0; r < RPW; ++r) {
                cvA[r] = __ldcs(cp + 64 + r * (IN_F / 4));
                amA[r] = __ldg(ap + 4 + r * AROW);
            }
        }
        consume(cvB, amB, 128);

        cp += 64;    // 2 chunks of 128 ints
        xp += 256;
        ap += 4;
    }

    // Reduce packed pairs, warp-reduce, store out[b, row]
    #pragma unroll
    for (int r = 0; r < RPW; ++r) {
        #pragma unroll
        for (int b = 0; b < NB; ++b) {
            float lo, hi;
            upk2(acc[r][b], lo, hi);
            float s = lo + hi;
            #pragma unroll
            for (int off = 16; off > 0; off >>= 1)
                s += __shfl_xor_sync(0xffffffffu, s, off);
            if (lane == 0) out[(size_t)b * OUT_F + row0 + r] = s;
        }
    }
}

extern "C" void kernel_launch(void* const* d_in, const int* in_sizes, int n_in,
                              void* d_out, int out_size) {
    const float* x      = (const float*)d_in[0];   // [8,1,4096] f32
    const int*   codes  = (const int*)d_in[1];     // [16384,4096] i32 (0..15)
    const float* absmax = (const float*)d_in[2];   // [16384,64] f32
    float*       out    = (float*)d_out;           // [8,1,16384] f32

    (void)in_sizes; (void)n_in; (void)out_size;
    nf4_qlinear_kernel<<<OUT_F / ROWS_PER_CTA, THREADS>>>(x, codes, absmax, out);
}

// round 11
// speedup vs baseline: 1.1890x; 1.1890x over previous
#include <cuda_runtime.h>
#include <cstdint>

#define IN_F  4096
#define OUT_F 16384
#define NB    8      // batch vectors
#define NP    (NB/2) // batch pairs
#define RPW   4      // rows per warp
#define WARPS 8
#define THREADS (WARPS * 32)          // 256
#define ROWS_PER_CTA (RPW * WARPS)    // 32
#define NCHUNK (IN_F / 128)           // 32 chunks (4 cols/lane each)
#define AROW   (IN_F / 64)            // absmax row stride (64)

__constant__ float NF4_CODE[16] = {
    -1.0f, -0.6961928009986877f, -0.5250730514526367f, -0.39491748809814453f,
    -0.28444138169288635f, -0.18477343022823334f, -0.09105003625154495f, 0.0f,
    0.07958029955625534f, 0.16093020141124725f, 0.24611230194568634f,
    0.33791524171829224f, 0.44070982933044434f, 0.5626170039176941f,
    0.7229568362236023f, 1.0f};

typedef unsigned long long ull;

// cross-batch packed x: g_xT[p*IN_F + col] = (x[2p][col], x[2p+1][col])
__device__ ull g_xT[NP * IN_F];

__device__ __forceinline__ ull pk2(float lo, float hi) {
    ull r;
    asm("mov.b64 %0, {%1, %2};" : "=l"(r)
        : "r"(__float_as_uint(lo)), "r"(__float_as_uint(hi)));
    return r;
}
__device__ __forceinline__ void upk2(ull v, float& lo, float& hi) {
    unsigned int a, b;
    asm("mov.b64 {%0, %1}, %2;" : "=r"(a), "=r"(b) : "l"(v));
    lo = __uint_as_float(a); hi = __uint_as_float(b);
}
__device__ __forceinline__ void fma2(ull& acc, ull a, ull b) {
    asm("fma.rn.f32x2 %0, %1, %2, %0;" : "+l"(acc) : "l"(a), "l"(b));
}
__device__ __forceinline__ ull mul2(ull a, ull b) {
    ull r;
    asm("mul.rn.f32x2 %0, %1, %2;" : "=l"(r) : "l"(a), "l"(b));
    return r;
}

// ---- pre-pass: build cross-batch packed x (runs once per launch, ~2us) ----
__global__ void xt_kernel(const float* __restrict__ x) {
    const int idx = blockIdx.x * 256 + threadIdx.x;   // 0 .. NP*IN_F-1
    const int p   = idx >> 12;
    const int col = idx & (IN_F - 1);
    g_xT[idx] = pk2(x[(2 * p) * IN_F + col], x[(2 * p + 1) * IN_F + col]);
}

// ---- consume one chunk: splat-table dequant + batch-pair FMAs ----
__device__ __forceinline__ void consume_chunk(
    ull (&acc)[RPW][NP], const int4* cv, const float* am,
    const ull* __restrict__ xq, const ull* tabS) {
    ull w[RPW][4];
    #pragma unroll
    for (int r = 0; r < RPW; ++r) {
        const ull a2 = pk2(am[r], am[r]);
        w[r][0] = mul2(tabS[cv[r].x], a2);
        w[r][1] = mul2(tabS[cv[r].y], a2);
        w[r][2] = mul2(tabS[cv[r].z], a2);
        w[r][3] = mul2(tabS[cv[r].w], a2);
    }
    #pragma unroll
    for (int p = 0; p < NP; ++p) {
        const ulonglong2 xv0 = *reinterpret_cast<const ulonglong2*>(
            xq + (size_t)p * IN_F);
        const ulonglong2 xv1 = *reinterpret_cast<const ulonglong2*>(
            xq + (size_t)p * IN_F + 2);
        #pragma unroll
        for (int r = 0; r < RPW; ++r) {
            fma2(acc[r][p], w[r][0], xv0.x);
            fma2(acc[r][p], w[r][1], xv0.y);
            fma2(acc[r][p], w[r][2], xv1.x);
            fma2(acc[r][p], w[r][3], xv1.y);
        }
    }
}

__global__ __launch_bounds__(THREADS, 2)
void nf4_qlinear_kernel(const int*   __restrict__ codes,
                        const float* __restrict__ absmax,
                        float*       __restrict__ out) {
    // splat NF4 table: tabS[c] = (nf4[c], nf4[c]); 16 entries, each in its
    // own 8B bank-pair -> LDS.64 is conflict-free for ANY code pattern
    __shared__ ull tabS[16];
    const int tid  = threadIdx.x;
    const int lane = tid & 31;
    const int warp = tid >> 5;
    if (tid < 16) tabS[tid] = pk2(NF4_CODE[tid], NF4_CODE[tid]);
    __syncthreads();

    const int row0   = blockIdx.x * ROWS_PER_CTA + warp * RPW;
    const int sel_hi = (lane >= 16);

    // pointer-bump bases (all loads reg + const-immediate)
    const int4*  cp = reinterpret_cast<const int4*>(
                          codes + (size_t)row0 * IN_F) + lane;
    const float* ap = absmax + (size_t)row0 * AROW + sel_hi;
    const ull*   xp = g_xT + lane * 4;

    ull acc[RPW][NP];    // acc[r][p] packs (batch 2p, batch 2p+1)
    #pragma unroll
    for (int r = 0; r < RPW; ++r)
        #pragma unroll
        for (int p = 0; p < NP; ++p) acc[r][p] = 0ULL;

    // distance-1 double-buffered prefetch, unrolled x2 (no buffer copies)
    int4  cvA[RPW], cvB[RPW];
    float amA[RPW], amB[RPW];
    #pragma unroll
    for (int r = 0; r < RPW; ++r) {
        cvA[r] = __ldcs(cp + r * (IN_F / 4));
        amA[r] = __ldg(ap + r * AROW);
    }

    #pragma unroll 1
    for (int j = 0; j < NCHUNK; j += 2) {
        #pragma unroll
        for (int r = 0; r < RPW; ++r) {                 // prefetch chunk j+1
            cvB[r] = __ldcs(cp + 32 + r * (IN_F / 4));
            amB[r] = __ldg(ap + 2 + r * AROW);
        }
        consume_chunk(acc, cvA, amA, xp, tabS);

        if (j + 2 < NCHUNK) {
            #pragma unroll
            for (int r = 0; r < RPW; ++r) {             // prefetch chunk j+2
                cvA[r] = __ldcs(cp + 64 + r * (IN_F / 4));
                amA[r] = __ldg(ap + 4 + r * AROW);
            }
        }
        consume_chunk(acc, cvB, amB, xp + 128, tabS);

        cp += 64;
        ap += 4;
        xp += 256;
    }

    // warp-reduce packed (even,odd) batch sums, store
    #pragma unroll
    for (int r = 0; r < RPW; ++r) {
        #pragma unroll
        for (int p = 0; p < NP; ++p) {
            float se, so;
            upk2(acc[r][p], se, so);
            #pragma unroll
            for (int off = 16; off > 0; off >>= 1) {
                se += __shfl_xor_sync(0xffffffffu, se, off);
                so += __shfl_xor_sync(0xffffffffu, so, off);
            }
            if (lane == 0) {
                out[(size_t)(2 * p)     * OUT_F + row0 + r] = se;
                out[(size_t)(2 * p + 1) * OUT_F + row0 + r] = so;
            }
        }
    }
}

extern "C" void kernel_launch(void* const* d_in, const int* in_sizes, int n_in,
                              void* d_out, int out_size) {
    const float* x      = (const float*)d_in[0];   // [8,1,4096] f32
    const int*   codes  = (const int*)d_in[1];     // [16384,4096] i32 (0..15)
    const float* absmax = (const float*)d_in[2];   // [16384,64] f32
    float*       out    = (float*)d_out;           // [8,1,16384] f32

    (void)in_sizes; (void)n_in; (void)out_size;
    xt_kernel<<<(NP * IN_F) / 256, 256>>>(x);
    nf4_qlinear_kernel<<<OUT_F / ROWS_PER_CTA, THREADS>>>(codes, absmax, out);
}